// round 1
// baseline (speedup 1.0000x reference)
#include <cuda_runtime.h>

// Problem constants (fixed by the benchmark setup)
#define BATCH 16
#define V     2048
#define F     64
#define HID   64
#define KNN   30
#define NPTS  (BATCH * V)   // 32768

// ---------------- device scratch (static allocation, no cudaMalloc) ----------------
__device__ float g_dist[(size_t)BATCH * V * V];   // 256 MB distance matrix
__device__ float g_sq[NPTS];                      // squared norms
__device__ int   g_idx[NPTS * KNN];               // global neighbor indices
__device__ float g_C[NPTS * HID];                 // x @ (W1a+W1b) + b1
__device__ float g_P[NPTS * HID];                 // x @ W1b

// ---------------- kernel 1: squared norms ----------------
// blockDim (32,8): one warp per point, coalesced reads, warp reduce.
__global__ void sq_kernel(const float* __restrict__ x) {
    int v = blockIdx.x * 8 + threadIdx.y;
    int l = threadIdx.x;
    float a = x[v * F + l];
    float b = x[v * F + 32 + l];
    float s = a * a + b * b;
    #pragma unroll
    for (int o = 16; o; o >>= 1) s += __shfl_xor_sync(0xFFFFFFFFu, s, o);
    if (l == 0) g_sq[v] = s;
}

// ---------------- kernel 2: distance matrix (batched GEMM) ----------------
// Block computes a 64x64 tile of D[b] = sq_i + sq_j - 2 * Xi . Xj.
// Tiles stored k-major in smem (pad 68 for alignment + conflict-free float4).
__global__ __launch_bounds__(256) void dist_kernel(const float* __restrict__ x) {
    __shared__ __align__(16) float Xi[64][68];
    __shared__ __align__(16) float Xj[64][68];
    const int b  = blockIdx.z;
    const int i0 = blockIdx.y * 64;
    const int j0 = blockIdx.x * 64;
    const int tid = threadIdx.x;
    const float* xb = x + (size_t)b * V * F;

    for (int t = tid; t < 64 * 64; t += 256) {
        int v = t >> 6, f = t & 63;
        Xi[f][v] = xb[(i0 + v) * F + f];
        Xj[f][v] = xb[(j0 + v) * F + f];
    }
    __syncthreads();

    const int tx = tid & 15, ty = tid >> 4;
    const int r = ty * 4, c = tx * 4;
    float acc[4][4] = {};

    #pragma unroll 16
    for (int k = 0; k < 64; k++) {
        float4 a4 = *(const float4*)&Xi[k][r];
        float4 b4 = *(const float4*)&Xj[k][c];
        float av[4] = {a4.x, a4.y, a4.z, a4.w};
        float bv[4] = {b4.x, b4.y, b4.z, b4.w};
        #pragma unroll
        for (int ii = 0; ii < 4; ii++)
            #pragma unroll
            for (int jj = 0; jj < 4; jj++)
                acc[ii][jj] = fmaf(av[ii], bv[jj], acc[ii][jj]);
    }

    float sqi[4], sqj[4];
    #pragma unroll
    for (int u = 0; u < 4; u++) {
        sqi[u] = g_sq[b * V + i0 + r + u];
        sqj[u] = g_sq[b * V + j0 + c + u];
    }
    #pragma unroll
    for (int ii = 0; ii < 4; ii++) {
        float4 o;
        o.x = sqi[ii] + sqj[0] - 2.0f * acc[ii][0];
        o.y = sqi[ii] + sqj[1] - 2.0f * acc[ii][1];
        o.z = sqi[ii] + sqj[2] - 2.0f * acc[ii][2];
        o.w = sqi[ii] + sqj[3] - 2.0f * acc[ii][3];
        *(float4*)&g_dist[((size_t)b * V + i0 + r + ii) * V + j0 + c] = o;
    }
}

// ---------------- kernel 3: top-(K+1) selection, drop first (= self) ----------------
// One block (256 threads) per query row. Iterative argmin with smallest-index
// tie-break, matching jax.lax.top_k ordering semantics.
__global__ __launch_bounds__(256) void select_kernel() {
    const int q = blockIdx.x;            // global point index
    const int b = q >> 11;               // batch
    const int tid = threadIdx.x;
    const float* row = g_dist + (size_t)q * V;

    float dv[8];
    #pragma unroll
    for (int s = 0; s < 8; s++) dv[s] = row[tid + 256 * s];

    __shared__ float sval[8];
    __shared__ int   sidx[8];
    __shared__ int   swin;

    for (int it = 0; it < KNN + 1; it++) {
        // per-thread argmin (s ascending => smallest index kept on ties)
        float bvv = dv[0];
        int bs = 0;
        #pragma unroll
        for (int s = 1; s < 8; s++)
            if (dv[s] < bvv) { bvv = dv[s]; bs = s; }
        int bj = tid + 256 * bs;

        // warp argmin with index tie-break
        #pragma unroll
        for (int o = 16; o; o >>= 1) {
            float ov = __shfl_xor_sync(0xFFFFFFFFu, bvv, o);
            int   oj = __shfl_xor_sync(0xFFFFFFFFu, bj, o);
            if (ov < bvv || (ov == bvv && oj < bj)) { bvv = ov; bj = oj; }
        }
        int w = tid >> 5;
        if ((tid & 31) == 0) { sval[w] = bvv; sidx[w] = bj; }
        __syncthreads();
        if (tid < 8) {
            bvv = sval[tid]; bj = sidx[tid];
            #pragma unroll
            for (int o = 4; o; o >>= 1) {
                float ov = __shfl_xor_sync(0xFFu, bvv, o);
                int   oj = __shfl_xor_sync(0xFFu, bj, o);
                if (ov < bvv || (ov == bvv && oj < bj)) { bvv = ov; bj = oj; }
            }
            if (tid == 0) {
                swin = bj;
                if (it > 0) g_idx[q * KNN + (it - 1)] = (b << 11) + bj;  // global idx
            }
        }
        __syncthreads();
        int wj = swin;
        if ((wj & 255) == tid) dv[wj >> 8] = 3.4e38f;   // remove winner
    }
}

// ---------------- kernel 4: per-vertex C = x@(W1a+W1b)+b1, P = x@W1b ----------------
// Block: 32 vertices, 256 threads; thread = (vertex, 8 cols) for both outputs.
__global__ __launch_bounds__(256) void cp_kernel(const float* __restrict__ x,
                                                 const float* __restrict__ W1,
                                                 const float* __restrict__ b1) {
    __shared__ float Xs[32][65];
    __shared__ __align__(16) float Wc[64][64];
    __shared__ __align__(16) float Wp[64][64];
    const int v0g = blockIdx.x * 32;
    const int tid = threadIdx.x;

    for (int t = tid; t < 32 * 64; t += 256) {
        int v = t >> 6, f = t & 63;
        Xs[v][f] = x[(v0g + v) * F + f];
    }
    for (int t = tid; t < 64 * 64; t += 256) {
        int f = t >> 6, j = t & 63;
        float wb = W1[(F + f) * HID + j];
        Wc[f][j] = W1[f * HID + j] + wb;
        Wp[f][j] = wb;
    }
    __syncthreads();

    const int jg = tid & 7, v = tid >> 3;
    const int j = jg * 8;
    float aC[8] = {}, aP[8] = {};
    #pragma unroll 8
    for (int f = 0; f < 64; f++) {
        float xv = Xs[v][f];
        float4 c0 = *(const float4*)&Wc[f][j];
        float4 c1 = *(const float4*)&Wc[f][j + 4];
        float4 p0 = *(const float4*)&Wp[f][j];
        float4 p1 = *(const float4*)&Wp[f][j + 4];
        aC[0] = fmaf(xv, c0.x, aC[0]); aC[1] = fmaf(xv, c0.y, aC[1]);
        aC[2] = fmaf(xv, c0.z, aC[2]); aC[3] = fmaf(xv, c0.w, aC[3]);
        aC[4] = fmaf(xv, c1.x, aC[4]); aC[5] = fmaf(xv, c1.y, aC[5]);
        aC[6] = fmaf(xv, c1.z, aC[6]); aC[7] = fmaf(xv, c1.w, aC[7]);
        aP[0] = fmaf(xv, p0.x, aP[0]); aP[1] = fmaf(xv, p0.y, aP[1]);
        aP[2] = fmaf(xv, p0.z, aP[2]); aP[3] = fmaf(xv, p0.w, aP[3]);
        aP[4] = fmaf(xv, p1.x, aP[4]); aP[5] = fmaf(xv, p1.y, aP[5]);
        aP[6] = fmaf(xv, p1.z, aP[6]); aP[7] = fmaf(xv, p1.w, aP[7]);
    }
    float4 bb0 = *(const float4*)&b1[j];
    float4 bb1 = *(const float4*)&b1[j + 4];
    float4 oc0 = {aC[0] + bb0.x, aC[1] + bb0.y, aC[2] + bb0.z, aC[3] + bb0.w};
    float4 oc1 = {aC[4] + bb1.x, aC[5] + bb1.y, aC[6] + bb1.z, aC[7] + bb1.w};
    float4 op0 = {aP[0], aP[1], aP[2], aP[3]};
    float4 op1 = {aP[4], aP[5], aP[6], aP[7]};
    *(float4*)&g_C[(v0g + v) * HID + j]     = oc0;
    *(float4*)&g_C[(v0g + v) * HID + j + 4] = oc1;
    *(float4*)&g_P[(v0g + v) * HID + j]     = op0;
    *(float4*)&g_P[(v0g + v) * HID + j + 4] = op1;
}

// ---------------- kernel 5: edge MLP (layers 1..3) + max aggregate ----------------
// Block: 2 vertices (60 edges padded to 64 rows), 256 threads, dynamic smem:
//   W2s[64*64] | W3s[64*64] | h1s[2*32*65] | h2s[2*32*65] | Cs[2*64]
__global__ __launch_bounds__(256) void edge_kernel(const float* __restrict__ W2,
                                                   const float* __restrict__ b2,
                                                   const float* __restrict__ W3,
                                                   const float* __restrict__ b3,
                                                   float* __restrict__ out) {
    extern __shared__ __align__(16) float sm[];
    float* W2s = sm;                      // 4096
    float* W3s = sm + 4096;               // 4096
    float* h1s = sm + 8192;               // 2*32*65 = 4160
    float* h2s = h1s + 4160;              // 4160
    float* Cs  = h2s + 4160;              // 128

    const int v0g = blockIdx.x * 2;
    const int tid = threadIdx.x;

    for (int t = tid; t < 64 * 64; t += 256) {
        W2s[t] = W2[t];
        W3s[t] = W3[t];
    }
    if (tid < 128) Cs[tid] = g_C[(v0g + (tid >> 6)) * HID + (tid & 63)];
    __syncthreads();

    // layer 1: h1 = relu(C[v] - P[nbr]); padded edge rows (30,31) = 0
    for (int t = tid; t < 2 * 32 * 64; t += 256) {
        int v = t >> 11, rem = t & 2047, e = rem >> 6, i = rem & 63;
        float h = 0.0f;
        if (e < KNN) {
            int nbr = g_idx[(v0g + v) * KNN + e];
            h = fmaxf(Cs[v * 64 + i] - g_P[nbr * HID + i], 0.0f);
        }
        h1s[(v * 32 + e) * 65 + i] = h;
    }
    __syncthreads();

    const int v_l = tid >> 7;
    const int r   = tid & 127;
    const int ep  = r >> 3;
    const int jg  = r & 7;
    const int e0  = ep * 2, e1 = e0 + 1;
    const int j   = jg * 8;

    // ---- layer 2 ----
    {
        float4 bA = *(const float4*)&b2[j];
        float4 bB = *(const float4*)&b2[j + 4];
        float acc0[8] = {bA.x, bA.y, bA.z, bA.w, bB.x, bB.y, bB.z, bB.w};
        float acc1[8] = {bA.x, bA.y, bA.z, bA.w, bB.x, bB.y, bB.z, bB.w};
        const float* h0p = h1s + (v_l * 32 + e0) * 65;
        const float* h1p = h1s + (v_l * 32 + e1) * 65;
        #pragma unroll 8
        for (int i = 0; i < 64; i++) {
            float h0 = h0p[i], h1v = h1p[i];
            float4 w0 = *(const float4*)&W2s[i * 64 + j];
            float4 w1 = *(const float4*)&W2s[i * 64 + j + 4];
            acc0[0] = fmaf(h0, w0.x, acc0[0]); acc0[1] = fmaf(h0, w0.y, acc0[1]);
            acc0[2] = fmaf(h0, w0.z, acc0[2]); acc0[3] = fmaf(h0, w0.w, acc0[3]);
            acc0[4] = fmaf(h0, w1.x, acc0[4]); acc0[5] = fmaf(h0, w1.y, acc0[5]);
            acc0[6] = fmaf(h0, w1.z, acc0[6]); acc0[7] = fmaf(h0, w1.w, acc0[7]);
            acc1[0] = fmaf(h1v, w0.x, acc1[0]); acc1[1] = fmaf(h1v, w0.y, acc1[1]);
            acc1[2] = fmaf(h1v, w0.z, acc1[2]); acc1[3] = fmaf(h1v, w0.w, acc1[3]);
            acc1[4] = fmaf(h1v, w1.x, acc1[4]); acc1[5] = fmaf(h1v, w1.y, acc1[5]);
            acc1[6] = fmaf(h1v, w1.z, acc1[6]); acc1[7] = fmaf(h1v, w1.w, acc1[7]);
        }
        float* o0 = h2s + (v_l * 32 + e0) * 65 + j;
        float* o1 = h2s + (v_l * 32 + e1) * 65 + j;
        #pragma unroll
        for (int u = 0; u < 8; u++) {
            o0[u] = fmaxf(acc0[u], 0.0f);
            o1[u] = fmaxf(acc1[u], 0.0f);
        }
    }
    __syncthreads();

    // ---- layer 3 + per-thread masked max over its 2 edges ----
    float lm[8];
    {
        float4 bA = *(const float4*)&b3[j];
        float4 bB = *(const float4*)&b3[j + 4];
        float acc0[8] = {bA.x, bA.y, bA.z, bA.w, bB.x, bB.y, bB.z, bB.w};
        float acc1[8] = {bA.x, bA.y, bA.z, bA.w, bB.x, bB.y, bB.z, bB.w};
        const float* h0p = h2s + (v_l * 32 + e0) * 65;
        const float* h1p = h2s + (v_l * 32 + e1) * 65;
        #pragma unroll 8
        for (int i = 0; i < 64; i++) {
            float h0 = h0p[i], h1v = h1p[i];
            float4 w0 = *(const float4*)&W3s[i * 64 + j];
            float4 w1 = *(const float4*)&W3s[i * 64 + j + 4];
            acc0[0] = fmaf(h0, w0.x, acc0[0]); acc0[1] = fmaf(h0, w0.y, acc0[1]);
            acc0[2] = fmaf(h0, w0.z, acc0[2]); acc0[3] = fmaf(h0, w0.w, acc0[3]);
            acc0[4] = fmaf(h0, w1.x, acc0[4]); acc0[5] = fmaf(h0, w1.y, acc0[5]);
            acc0[6] = fmaf(h0, w1.z, acc0[6]); acc0[7] = fmaf(h0, w1.w, acc0[7]);
            acc1[0] = fmaf(h1v, w0.x, acc1[0]); acc1[1] = fmaf(h1v, w0.y, acc1[1]);
            acc1[2] = fmaf(h1v, w0.z, acc1[2]); acc1[3] = fmaf(h1v, w0.w, acc1[3]);
            acc1[4] = fmaf(h1v, w1.x, acc1[4]); acc1[5] = fmaf(h1v, w1.y, acc1[5]);
            acc1[6] = fmaf(h1v, w1.z, acc1[6]); acc1[7] = fmaf(h1v, w1.w, acc1[7]);
        }
        #pragma unroll
        for (int u = 0; u < 8; u++) {
            float m = -1e30f;
            if (e0 < KNN) m = fmaxf(acc0[u], 0.0f);
            if (e1 < KNN) m = fmaxf(m, fmaxf(acc1[u], 0.0f));
            lm[u] = m;
        }
    }
    // reduction buffer reuses h1s (all h1s reads completed before prior sync)
    #pragma unroll
    for (int u = 0; u < 8; u++) h1s[(v_l * 32 + ep) * 65 + j + u] = lm[u];
    __syncthreads();

    if (tid < 128) {
        int v = tid >> 6, jj = tid & 63;
        float m = h1s[(v * 32 + 0) * 65 + jj];
        #pragma unroll
        for (int p = 1; p < 16; p++) m = fmaxf(m, h1s[(v * 32 + p) * 65 + jj]);
        out[(v0g + v) * HID + jj] = m;
    }
}

// ---------------- launch ----------------
extern "C" void kernel_launch(void* const* d_in, const int* in_sizes, int n_in,
                              void* d_out, int out_size) {
    (void)in_sizes; (void)n_in; (void)out_size;
    const float* x  = (const float*)d_in[0];
    // d_in[1] = rowsplits (uniform, unused)
    const float* W1 = (const float*)d_in[2];
    const float* b1 = (const float*)d_in[3];
    const float* W2 = (const float*)d_in[4];
    const float* b2 = (const float*)d_in[5];
    const float* W3 = (const float*)d_in[6];
    const float* b3 = (const float*)d_in[7];
    float* out = (float*)d_out;

    const int EDGE_SMEM = (4096 + 4096 + 4160 + 4160 + 128) * 4;  // 66560 B
    cudaFuncSetAttribute(edge_kernel, cudaFuncAttributeMaxDynamicSharedMemorySize,
                         EDGE_SMEM);

    sq_kernel<<<NPTS / 8, dim3(32, 8)>>>(x);
    dist_kernel<<<dim3(V / 64, V / 64, BATCH), 256>>>(x);
    select_kernel<<<NPTS, 256>>>();
    cp_kernel<<<NPTS / 32, 256>>>(x, W1, b1);
    edge_kernel<<<NPTS / 2, 256, EDGE_SMEM>>>(W2, b2, W3, b3, out);
}

// round 2
// speedup vs baseline: 1.7457x; 1.7457x over previous
#include <cuda_runtime.h>

#define BATCH 16
#define V     2048
#define F     64
#define HID   64
#define KNN   30
#define NPTS  (BATCH * V)   // 32768

// ---------------- device scratch ----------------
__device__ float g_dist[(size_t)BATCH * V * V];   // 256 MB
__device__ float g_sq[NPTS];
__device__ int   g_idx[NPTS * KNN];
__device__ float g_C[NPTS * HID];   // x @ (W1a+W1b) + b1
__device__ float g_P[NPTS * HID];   // x @ W1b

// ---------------- kernel 1: squared norms ----------------
__global__ void sq_kernel(const float* __restrict__ x) {
    int v = blockIdx.x * 8 + threadIdx.y;
    int l = threadIdx.x;
    float a = x[v * F + l];
    float b = x[v * F + 32 + l];
    float s = a * a + b * b;
    #pragma unroll
    for (int o = 16; o; o >>= 1) s += __shfl_xor_sync(0xFFFFFFFFu, s, o);
    if (l == 0) g_sq[v] = s;
}

// ---------------- kernel 2: symmetric distance GEMM ----------------
// Upper-triangular 128x128 tiles, 8x8 register tile per thread,
// mirror-store the transposed tile for ti != tj.
#define TS 136   // smem row stride (words), 16B-aligned
__global__ __launch_bounds__(256) void dist_kernel(const float* __restrict__ x) {
    extern __shared__ __align__(16) float sm[];
    float* Xi = sm;            // [64][TS]
    float* Xj = sm + 64 * TS;  // [64][TS]
    const int b = blockIdx.y;
    // map blockIdx.x -> (ti, tj), ti <= tj, 16 tiles per dim -> 136 pairs
    int p = blockIdx.x, ti = 0;
    while (p >= 16 - ti) { p -= 16 - ti; ti++; }
    const int tj = ti + p;
    const int i0 = ti * 128, j0 = tj * 128;
    const int tid = threadIdx.x;
    const float* xb = x + (size_t)b * V * F;

    for (int t = tid; t < 8192; t += 256) {
        int f = t & 63, v = t >> 6;
        Xi[f * TS + v] = xb[(i0 + v) * F + f];
        Xj[f * TS + v] = xb[(j0 + v) * F + f];
    }
    __syncthreads();

    const int tx = tid & 15, ty = tid >> 4;
    const int rr = ty * 8, cc = tx * 8;
    float acc[8][8] = {};

    #pragma unroll 8
    for (int k = 0; k < 64; k++) {
        float4 a0 = *(const float4*)&Xi[k * TS + rr];
        float4 a1 = *(const float4*)&Xi[k * TS + rr + 4];
        float4 c0 = *(const float4*)&Xj[k * TS + cc];
        float4 c1 = *(const float4*)&Xj[k * TS + cc + 4];
        float av[8] = {a0.x, a0.y, a0.z, a0.w, a1.x, a1.y, a1.z, a1.w};
        float bv[8] = {c0.x, c0.y, c0.z, c0.w, c1.x, c1.y, c1.z, c1.w};
        #pragma unroll
        for (int ii = 0; ii < 8; ii++)
            #pragma unroll
            for (int jj = 0; jj < 8; jj++)
                acc[ii][jj] = fmaf(av[ii], bv[jj], acc[ii][jj]);
    }

    float sqi[8], sqj[8];
    #pragma unroll
    for (int u = 0; u < 8; u++) {
        sqi[u] = g_sq[b * V + i0 + rr + u];
        sqj[u] = g_sq[b * V + j0 + cc + u];
    }
    float* db = g_dist + (size_t)b * V * V;
    #pragma unroll
    for (int ii = 0; ii < 8; ii++) {
        float4 o0, o1;
        o0.x = sqi[ii] + sqj[0] - 2.0f * acc[ii][0];
        o0.y = sqi[ii] + sqj[1] - 2.0f * acc[ii][1];
        o0.z = sqi[ii] + sqj[2] - 2.0f * acc[ii][2];
        o0.w = sqi[ii] + sqj[3] - 2.0f * acc[ii][3];
        o1.x = sqi[ii] + sqj[4] - 2.0f * acc[ii][4];
        o1.y = sqi[ii] + sqj[5] - 2.0f * acc[ii][5];
        o1.z = sqi[ii] + sqj[6] - 2.0f * acc[ii][6];
        o1.w = sqi[ii] + sqj[7] - 2.0f * acc[ii][7];
        *(float4*)&db[(size_t)(i0 + rr + ii) * V + j0 + cc]     = o0;
        *(float4*)&db[(size_t)(i0 + rr + ii) * V + j0 + cc + 4] = o1;
    }
    if (ti != tj) {  // mirror
        #pragma unroll
        for (int jj = 0; jj < 8; jj++) {
            float4 o0, o1;
            o0.x = sqj[jj] + sqi[0] - 2.0f * acc[0][jj];
            o0.y = sqj[jj] + sqi[1] - 2.0f * acc[1][jj];
            o0.z = sqj[jj] + sqi[2] - 2.0f * acc[2][jj];
            o0.w = sqj[jj] + sqi[3] - 2.0f * acc[3][jj];
            o1.x = sqj[jj] + sqi[4] - 2.0f * acc[4][jj];
            o1.y = sqj[jj] + sqi[5] - 2.0f * acc[5][jj];
            o1.z = sqj[jj] + sqi[6] - 2.0f * acc[6][jj];
            o1.w = sqj[jj] + sqi[7] - 2.0f * acc[7][jj];
            *(float4*)&db[(size_t)(j0 + cc + jj) * V + i0 + rr]     = o0;
            *(float4*)&db[(size_t)(j0 + cc + jj) * V + i0 + rr + 4] = o1;
        }
    }
}

// ---------------- kernel 3: warp-per-row top-31 selection ----------------
// Values in registers (64/lane). Per iteration: 5-shfl argmin with
// (value, global index) lexicographic tie-break; winner lane promotes its
// cached 2nd-best, rescanning its 64 registers only when both consumed.
__global__ __launch_bounds__(256) void select_kernel() {
    const int warp = threadIdx.x >> 5, lane = threadIdx.x & 31;
    const int q = blockIdx.x * 8 + warp;
    const float4* r4 = (const float4*)(g_dist + (size_t)q * V);

    float v[64];
    #pragma unroll
    for (int s = 0; s < 16; s++) {
        float4 t = r4[s * 32 + lane];
        v[s * 4 + 0] = t.x; v[s * 4 + 1] = t.y;
        v[s * 4 + 2] = t.z; v[s * 4 + 3] = t.w;
    }
    unsigned long long removed = 0ULL;
    float b1v = v[0], b2v = 3.4e38f;
    int b1p = 0, b2p = 0;
    #pragma unroll
    for (int p = 1; p < 64; p++) {           // ascending p == ascending j
        float xv = v[p];
        if (xv < b1v)      { b2v = b1v; b2p = b1p; b1v = xv; b1p = p; }
        else if (xv < b2v) { b2v = xv; b2p = p; }
    }
    bool b2ok = true;
    const int base = (q >> 11) << 11;

    #pragma unroll 1
    for (int it = 0; it < KNN + 1; it++) {
        float bv = b1v;
        int bj = ((b1p >> 2) << 7) + (lane << 2) + (b1p & 3);
        #pragma unroll
        for (int off = 16; off; off >>= 1) {
            float ov = __shfl_xor_sync(0xFFFFFFFFu, bv, off);
            int   oj = __shfl_xor_sync(0xFFFFFFFFu, bj, off);
            if (ov < bv || (ov == bv && oj < bj)) { bv = ov; bj = oj; }
        }
        if (it > 0 && lane == 0) g_idx[q * KNN + it - 1] = base + bj;
        int wl = (bj >> 2) & 31;
        if (lane == wl) {
            int pw = ((bj >> 7) << 2) | (bj & 3);
            removed |= 1ULL << pw;
            if (b2ok) { b1v = b2v; b1p = b2p; b2ok = false; }
            else {
                b1v = 3.4e38f; b2v = 3.4e38f; b1p = 0; b2p = 0;
                #pragma unroll
                for (int pp = 0; pp < 64; pp++) {
                    if (!((removed >> pp) & 1ULL)) {
                        float xv = v[pp];
                        if (xv < b1v)      { b2v = b1v; b2p = b1p; b1v = xv; b1p = pp; }
                        else if (xv < b2v) { b2v = xv; b2p = pp; }
                    }
                }
                b2ok = true;
            }
        }
    }
}

// ---------------- kernel 4: cp as 128x128 GEMM tile ----------------
// [128 verts, 64] @ [64, 128] where cols 0-63 -> C (=x@(W1a+W1b)+b1),
// cols 64-127 -> P (=x@W1b). One weight load per 128 vertices.
__global__ __launch_bounds__(256) void cp_kernel(const float* __restrict__ x,
                                                 const float* __restrict__ W1,
                                                 const float* __restrict__ b1) {
    extern __shared__ __align__(16) float sm[];
    float* Xs = sm;            // [64][TS]
    float* Ws = sm + 64 * TS;  // [64][TS]
    const int v0 = blockIdx.x * 128;
    const int tid = threadIdx.x;

    for (int t = tid; t < 8192; t += 256) {
        int f = t & 63, v = t >> 6;
        Xs[f * TS + v] = x[(v0 + v) * F + f];
    }
    for (int t = tid; t < 4096; t += 256) {
        int f = t >> 6, j = t & 63;
        float wb = W1[(F + f) * HID + j];
        Ws[f * TS + j]      = W1[f * HID + j] + wb;
        Ws[f * TS + 64 + j] = wb;
    }
    __syncthreads();

    const int tx = tid & 15, ty = tid >> 4;
    const int rr = ty * 8, cc = tx * 8;
    float acc[8][8] = {};
    #pragma unroll 8
    for (int k = 0; k < 64; k++) {
        float4 a0 = *(const float4*)&Xs[k * TS + rr];
        float4 a1 = *(const float4*)&Xs[k * TS + rr + 4];
        float4 c0 = *(const float4*)&Ws[k * TS + cc];
        float4 c1 = *(const float4*)&Ws[k * TS + cc + 4];
        float av[8] = {a0.x, a0.y, a0.z, a0.w, a1.x, a1.y, a1.z, a1.w};
        float bv[8] = {c0.x, c0.y, c0.z, c0.w, c1.x, c1.y, c1.z, c1.w};
        #pragma unroll
        for (int ii = 0; ii < 8; ii++)
            #pragma unroll
            for (int jj = 0; jj < 8; jj++)
                acc[ii][jj] = fmaf(av[ii], bv[jj], acc[ii][jj]);
    }

    if (tx < 8) {  // C half: add bias
        float4 bb0 = *(const float4*)&b1[cc];
        float4 bb1 = *(const float4*)&b1[cc + 4];
        float bb[8] = {bb0.x, bb0.y, bb0.z, bb0.w, bb1.x, bb1.y, bb1.z, bb1.w};
        #pragma unroll
        for (int ii = 0; ii < 8; ii++) {
            float4 o0 = {acc[ii][0] + bb[0], acc[ii][1] + bb[1],
                         acc[ii][2] + bb[2], acc[ii][3] + bb[3]};
            float4 o1 = {acc[ii][4] + bb[4], acc[ii][5] + bb[5],
                         acc[ii][6] + bb[6], acc[ii][7] + bb[7]};
            *(float4*)&g_C[(v0 + rr + ii) * HID + cc]     = o0;
            *(float4*)&g_C[(v0 + rr + ii) * HID + cc + 4] = o1;
        }
    } else {
        #pragma unroll
        for (int ii = 0; ii < 8; ii++) {
            float4 o0 = {acc[ii][0], acc[ii][1], acc[ii][2], acc[ii][3]};
            float4 o1 = {acc[ii][4], acc[ii][5], acc[ii][6], acc[ii][7]};
            *(float4*)&g_P[(v0 + rr + ii) * HID + cc - 64]     = o0;
            *(float4*)&g_P[(v0 + rr + ii) * HID + cc - 64 + 4] = o1;
        }
    }
}

// ---------------- kernel 5: edge MLP + max aggregate (4 verts/block) ----------------
#define HS 68   // h-row stride (words), 16B aligned
__global__ __launch_bounds__(256) void edge_kernel(const float* __restrict__ W2,
                                                   const float* __restrict__ b2,
                                                   const float* __restrict__ W3,
                                                   const float* __restrict__ b3,
                                                   float* __restrict__ out) {
    extern __shared__ __align__(16) float sm[];
    float* W2s = sm;                    // 4096
    float* W3s = sm + 4096;             // 4096
    float* h1s = sm + 8192;             // 4*32*HS = 8704
    float* h2s = h1s + 4 * 32 * HS;     // 8704
    float* Cs  = h2s + 4 * 32 * HS;     // 256

    const int v0 = blockIdx.x * 4;
    const int tid = threadIdx.x;

    for (int t = tid; t < 4096; t += 256) { W2s[t] = W2[t]; W3s[t] = W3[t]; }
    Cs[tid] = g_C[v0 * HID + tid];   // 4 verts x 64
    __syncthreads();

    // layer 1: h1 = relu(C[v] - P[nbr]), pad rows 30,31 with 0
    for (int t = tid; t < 4 * 32 * 64; t += 256) {
        int v = t >> 11, e = (t >> 6) & 31, i = t & 63;
        float h = 0.0f;
        if (e < KNN) {
            int nbr = g_idx[(v0 + v) * KNN + e];
            h = fmaxf(Cs[v * 64 + i] - g_P[nbr * HID + i], 0.0f);
        }
        h1s[(v * 32 + e) * HS + i] = h;
    }
    __syncthreads();

    const int vl = tid >> 6, r = tid & 63;
    const int ep = r >> 3, jg = r & 7;
    const int j = jg * 8;
    const int ebase = ep * 4;
    const float* hp1 = h1s + (vl * 32 + ebase) * HS;
    const float* hp2 = h2s + (vl * 32 + ebase) * HS;

    // ---- layer 2 ----
    {
        float4 bA = *(const float4*)&b2[j];
        float4 bB = *(const float4*)&b2[j + 4];
        float bb[8] = {bA.x, bA.y, bA.z, bA.w, bB.x, bB.y, bB.z, bB.w};
        float acc[4][8];
        #pragma unroll
        for (int k = 0; k < 4; k++)
            #pragma unroll
            for (int u = 0; u < 8; u++) acc[k][u] = bb[u];
        #pragma unroll 8
        for (int i = 0; i < 64; i++) {
            float h0 = hp1[i], h1v = hp1[HS + i], h2v = hp1[2 * HS + i], h3v = hp1[3 * HS + i];
            float4 w0 = *(const float4*)&W2s[i * 64 + j];
            float4 w1 = *(const float4*)&W2s[i * 64 + j + 4];
            float wv[8] = {w0.x, w0.y, w0.z, w0.w, w1.x, w1.y, w1.z, w1.w};
            #pragma unroll
            for (int u = 0; u < 8; u++) {
                acc[0][u] = fmaf(h0,  wv[u], acc[0][u]);
                acc[1][u] = fmaf(h1v, wv[u], acc[1][u]);
                acc[2][u] = fmaf(h2v, wv[u], acc[2][u]);
                acc[3][u] = fmaf(h3v, wv[u], acc[3][u]);
            }
        }
        #pragma unroll
        for (int k = 0; k < 4; k++) {
            float4 o0 = {fmaxf(acc[k][0], 0.f), fmaxf(acc[k][1], 0.f),
                         fmaxf(acc[k][2], 0.f), fmaxf(acc[k][3], 0.f)};
            float4 o1 = {fmaxf(acc[k][4], 0.f), fmaxf(acc[k][5], 0.f),
                         fmaxf(acc[k][6], 0.f), fmaxf(acc[k][7], 0.f)};
            *(float4*)&h2s[(vl * 32 + ebase + k) * HS + j]     = o0;
            *(float4*)&h2s[(vl * 32 + ebase + k) * HS + j + 4] = o1;
        }
    }
    __syncthreads();

    // ---- layer 3 + per-thread masked max over its 4 edges ----
    float lm[8];
    {
        float4 bA = *(const float4*)&b3[j];
        float4 bB = *(const float4*)&b3[j + 4];
        float bb[8] = {bA.x, bA.y, bA.z, bA.w, bB.x, bB.y, bB.z, bB.w};
        float acc[4][8];
        #pragma unroll
        for (int k = 0; k < 4; k++)
            #pragma unroll
            for (int u = 0; u < 8; u++) acc[k][u] = bb[u];
        #pragma unroll 8
        for (int i = 0; i < 64; i++) {
            float h0 = hp2[i], h1v = hp2[HS + i], h2v = hp2[2 * HS + i], h3v = hp2[3 * HS + i];
            float4 w0 = *(const float4*)&W3s[i * 64 + j];
            float4 w1 = *(const float4*)&W3s[i * 64 + j + 4];
            float wv[8] = {w0.x, w0.y, w0.z, w0.w, w1.x, w1.y, w1.z, w1.w};
            #pragma unroll
            for (int u = 0; u < 8; u++) {
                acc[0][u] = fmaf(h0,  wv[u], acc[0][u]);
                acc[1][u] = fmaf(h1v, wv[u], acc[1][u]);
                acc[2][u] = fmaf(h2v, wv[u], acc[2][u]);
                acc[3][u] = fmaf(h3v, wv[u], acc[3][u]);
            }
        }
        #pragma unroll
        for (int u = 0; u < 8; u++) {
            float m = -1e30f;
            #pragma unroll
            for (int k = 0; k < 4; k++)
                if (ebase + k < KNN) m = fmaxf(m, fmaxf(acc[k][u], 0.f));
            lm[u] = m;
        }
    }
    // partial-max buffer reuses h1s
    {
        float4 o0 = {lm[0], lm[1], lm[2], lm[3]};
        float4 o1 = {lm[4], lm[5], lm[6], lm[7]};
        *(float4*)&h1s[(vl * 8 + ep) * HS + j]     = o0;
        *(float4*)&h1s[(vl * 8 + ep) * HS + j + 4] = o1;
    }
    __syncthreads();

    {
        int v = tid >> 6, col = tid & 63;
        float m = h1s[(v * 8 + 0) * HS + col];
        #pragma unroll
        for (int p = 1; p < 8; p++) m = fmaxf(m, h1s[(v * 8 + p) * HS + col]);
        out[(v0 + v) * HID + col] = m;
    }
}

// ---------------- launch ----------------
extern "C" void kernel_launch(void* const* d_in, const int* in_sizes, int n_in,
                              void* d_out, int out_size) {
    (void)in_sizes; (void)n_in; (void)out_size;
    const float* x  = (const float*)d_in[0];
    const float* W1 = (const float*)d_in[2];
    const float* b1 = (const float*)d_in[3];
    const float* W2 = (const float*)d_in[4];
    const float* b2 = (const float*)d_in[5];
    const float* W3 = (const float*)d_in[6];
    const float* b3 = (const float*)d_in[7];
    float* out = (float*)d_out;

    const int GEMM_SMEM = 2 * 64 * TS * 4;                         // 69632 B
    const int EDGE_SMEM = (4096 + 4096 + 2 * 4 * 32 * HS + 256) * 4;  // 103424 B
    static bool attr_done = false;
    if (!attr_done) {
        cudaFuncSetAttribute(dist_kernel, cudaFuncAttributeMaxDynamicSharedMemorySize, GEMM_SMEM);
        cudaFuncSetAttribute(cp_kernel,   cudaFuncAttributeMaxDynamicSharedMemorySize, GEMM_SMEM);
        cudaFuncSetAttribute(edge_kernel, cudaFuncAttributeMaxDynamicSharedMemorySize, EDGE_SMEM);
        attr_done = true;
    }

    sq_kernel<<<NPTS / 8, dim3(32, 8)>>>(x);
    dist_kernel<<<dim3(136, BATCH), 256, GEMM_SMEM>>>(x);
    select_kernel<<<NPTS / 8, 256>>>();
    cp_kernel<<<NPTS / 128, 256, GEMM_SMEM>>>(x, W1, b1);
    edge_kernel<<<NPTS / 4, 256, EDGE_SMEM>>>(W2, b2, W3, b3, out);
}

// round 6
// speedup vs baseline: 2.5388x; 1.4543x over previous
#include <cuda_runtime.h>

#define BATCH 16
#define V     2048
#define F     64
#define HID   64
#define KNN   30
#define NPTS  (BATCH * V)   // 32768

// ---------------- device scratch ----------------
__device__ float g_dist[(size_t)BATCH * V * V];   // 256 MB
__device__ float g_sq[NPTS];
__device__ int   g_idx[NPTS * KNN];
__device__ float g_C[NPTS * HID];   // x @ (W1a+W1b) + b1
__device__ float g_P[NPTS * HID];   // x @ W1b

// ---------------- tf32 helpers ----------------
__device__ __forceinline__ unsigned f2tf(float x) {
    unsigned r; asm("cvt.rna.tf32.f32 %0, %1;" : "=r"(r) : "f"(x)); return r;
}
__device__ __forceinline__ void mma1688(float& c0, float& c1, float& c2, float& c3,
                                        unsigned a0, unsigned a1, unsigned a2, unsigned a3,
                                        unsigned b0, unsigned b1) {
    asm("mma.sync.aligned.m16n8k8.row.col.f32.tf32.tf32.f32 "
        "{%0,%1,%2,%3},{%4,%5,%6,%7},{%8,%9},{%0,%1,%2,%3};"
        : "+f"(c0), "+f"(c1), "+f"(c2), "+f"(c3)
        : "r"(a0), "r"(a1), "r"(a2), "r"(a3), "r"(b0), "r"(b1));
}

// ---------------- kernel 1: squared norms ----------------
__global__ void sq_kernel(const float* __restrict__ x) {
    int v = blockIdx.x * 8 + threadIdx.y;
    int l = threadIdx.x;
    float a = x[v * F + l];
    float b = x[v * F + 32 + l];
    float s = a * a + b * b;
    #pragma unroll
    for (int o = 16; o; o >>= 1) s += __shfl_xor_sync(0xFFFFFFFFu, s, o);
    if (l == 0) g_sq[v] = s;
}

// ---------------- kernel 2: symmetric distance GEMM (fp32, exact) ----------------
#define TS 136
__global__ __launch_bounds__(256) void dist_kernel(const float* __restrict__ x) {
    extern __shared__ __align__(16) float sm[];
    float* Xi = sm;
    float* Xj = sm + 64 * TS;
    const int b = blockIdx.y;
    int p = blockIdx.x, ti = 0;
    while (p >= 16 - ti) { p -= 16 - ti; ti++; }
    const int tj = ti + p;
    const int i0 = ti * 128, j0 = tj * 128;
    const int tid = threadIdx.x;
    const float* xb = x + (size_t)b * V * F;

    for (int t = tid; t < 8192; t += 256) {
        int f = t & 63, v = t >> 6;
        Xi[f * TS + v] = xb[(i0 + v) * F + f];
        Xj[f * TS + v] = xb[(j0 + v) * F + f];
    }
    __syncthreads();

    const int tx = tid & 15, ty = tid >> 4;
    const int rr = ty * 8, cc = tx * 8;
    float acc[8][8] = {};

    #pragma unroll 8
    for (int k = 0; k < 64; k++) {
        float4 a0 = *(const float4*)&Xi[k * TS + rr];
        float4 a1 = *(const float4*)&Xi[k * TS + rr + 4];
        float4 c0 = *(const float4*)&Xj[k * TS + cc];
        float4 c1 = *(const float4*)&Xj[k * TS + cc + 4];
        float av[8] = {a0.x, a0.y, a0.z, a0.w, a1.x, a1.y, a1.z, a1.w};
        float bv[8] = {c0.x, c0.y, c0.z, c0.w, c1.x, c1.y, c1.z, c1.w};
        #pragma unroll
        for (int ii = 0; ii < 8; ii++)
            #pragma unroll
            for (int jj = 0; jj < 8; jj++)
                acc[ii][jj] = fmaf(av[ii], bv[jj], acc[ii][jj]);
    }

    float sqi[8], sqj[8];
    #pragma unroll
    for (int u = 0; u < 8; u++) {
        sqi[u] = g_sq[b * V + i0 + rr + u];
        sqj[u] = g_sq[b * V + j0 + cc + u];
    }
    float* db = g_dist + (size_t)b * V * V;
    #pragma unroll
    for (int ii = 0; ii < 8; ii++) {
        float4 o0, o1;
        o0.x = sqi[ii] + sqj[0] - 2.0f * acc[ii][0];
        o0.y = sqi[ii] + sqj[1] - 2.0f * acc[ii][1];
        o0.z = sqi[ii] + sqj[2] - 2.0f * acc[ii][2];
        o0.w = sqi[ii] + sqj[3] - 2.0f * acc[ii][3];
        o1.x = sqi[ii] + sqj[4] - 2.0f * acc[ii][4];
        o1.y = sqi[ii] + sqj[5] - 2.0f * acc[ii][5];
        o1.z = sqi[ii] + sqj[6] - 2.0f * acc[ii][6];
        o1.w = sqi[ii] + sqj[7] - 2.0f * acc[ii][7];
        *(float4*)&db[(size_t)(i0 + rr + ii) * V + j0 + cc]     = o0;
        *(float4*)&db[(size_t)(i0 + rr + ii) * V + j0 + cc + 4] = o1;
    }
    if (ti != tj) {
        #pragma unroll
        for (int jj = 0; jj < 8; jj++) {
            float4 o0, o1;
            o0.x = sqj[jj] + sqi[0] - 2.0f * acc[0][jj];
            o0.y = sqj[jj] + sqi[1] - 2.0f * acc[1][jj];
            o0.z = sqj[jj] + sqi[2] - 2.0f * acc[2][jj];
            o0.w = sqj[jj] + sqi[3] - 2.0f * acc[3][jj];
            o1.x = sqj[jj] + sqi[4] - 2.0f * acc[4][jj];
            o1.y = sqj[jj] + sqi[5] - 2.0f * acc[5][jj];
            o1.z = sqj[jj] + sqi[6] - 2.0f * acc[6][jj];
            o1.w = sqj[jj] + sqi[7] - 2.0f * acc[7][jj];
            *(float4*)&db[(size_t)(j0 + cc + jj) * V + i0 + rr]     = o0;
            *(float4*)&db[(size_t)(j0 + cc + jj) * V + i0 + rr + 4] = o1;
        }
    }
}

// ---------------- kernel 3: warp-per-row top-31 selection ----------------
__global__ __launch_bounds__(256) void select_kernel() {
    const int warp = threadIdx.x >> 5, lane = threadIdx.x & 31;
    const int q = blockIdx.x * 8 + warp;
    const float4* r4 = (const float4*)(g_dist + (size_t)q * V);

    float v[64];
    #pragma unroll
    for (int s = 0; s < 16; s++) {
        float4 t = r4[s * 32 + lane];
        v[s * 4 + 0] = t.x; v[s * 4 + 1] = t.y;
        v[s * 4 + 2] = t.z; v[s * 4 + 3] = t.w;
    }
    unsigned long long removed = 0ULL;
    float b1v = v[0], b2v = 3.4e38f;
    int b1p = 0, b2p = 0;
    #pragma unroll
    for (int p = 1; p < 64; p++) {
        float xv = v[p];
        if (xv < b1v)      { b2v = b1v; b2p = b1p; b1v = xv; b1p = p; }
        else if (xv < b2v) { b2v = xv; b2p = p; }
    }
    bool b2ok = true;
    const int base = (q >> 11) << 11;

    #pragma unroll 1
    for (int it = 0; it < KNN + 1; it++) {
        float bv = b1v;
        int bj = ((b1p >> 2) << 7) + (lane << 2) + (b1p & 3);
        #pragma unroll
        for (int off = 16; off; off >>= 1) {
            float ov = __shfl_xor_sync(0xFFFFFFFFu, bv, off);
            int   oj = __shfl_xor_sync(0xFFFFFFFFu, bj, off);
            if (ov < bv || (ov == bv && oj < bj)) { bv = ov; bj = oj; }
        }
        if (it > 0 && lane == 0) g_idx[q * KNN + it - 1] = base + bj;
        int wl = (bj >> 2) & 31;
        if (lane == wl) {
            int pw = ((bj >> 7) << 2) | (bj & 3);
            removed |= 1ULL << pw;
            if (b2ok) { b1v = b2v; b1p = b2p; b2ok = false; }
            else {
                b1v = 3.4e38f; b2v = 3.4e38f; b1p = 0; b2p = 0;
                #pragma unroll
                for (int pp = 0; pp < 64; pp++) {
                    if (!((removed >> pp) & 1ULL)) {
                        float xv = v[pp];
                        if (xv < b1v)      { b2v = b1v; b2p = b1p; b1v = xv; b1p = pp; }
                        else if (xv < b2v) { b2v = xv; b2p = pp; }
                    }
                }
                b2ok = true;
            }
        }
    }
}

// ---------------- kernel 4: cp as 128x128 GEMM tile (fp32, exact) ----------------
__global__ __launch_bounds__(256) void cp_kernel(const float* __restrict__ x,
                                                 const float* __restrict__ W1,
                                                 const float* __restrict__ b1) {
    extern __shared__ __align__(16) float sm[];
    float* Xs = sm;
    float* Ws = sm + 64 * TS;
    const int v0 = blockIdx.x * 128;
    const int tid = threadIdx.x;

    for (int t = tid; t < 8192; t += 256) {
        int f = t & 63, v = t >> 6;
        Xs[f * TS + v] = x[(v0 + v) * F + f];
    }
    for (int t = tid; t < 4096; t += 256) {
        int f = t >> 6, j = t & 63;
        float wb = W1[(F + f) * HID + j];
        Ws[f * TS + j]      = W1[f * HID + j] + wb;
        Ws[f * TS + 64 + j] = wb;
    }
    __syncthreads();

    const int tx = tid & 15, ty = tid >> 4;
    const int rr = ty * 8, cc = tx * 8;
    float acc[8][8] = {};
    #pragma unroll 8
    for (int k = 0; k < 64; k++) {
        float4 a0 = *(const float4*)&Xs[k * TS + rr];
        float4 a1 = *(const float4*)&Xs[k * TS + rr + 4];
        float4 c0 = *(const float4*)&Ws[k * TS + cc];
        float4 c1 = *(const float4*)&Ws[k * TS + cc + 4];
        float av[8] = {a0.x, a0.y, a0.z, a0.w, a1.x, a1.y, a1.z, a1.w};
        float bv[8] = {c0.x, c0.y, c0.z, c0.w, c1.x, c1.y, c1.z, c1.w};
        #pragma unroll
        for (int ii = 0; ii < 8; ii++)
            #pragma unroll
            for (int jj = 0; jj < 8; jj++)
                acc[ii][jj] = fmaf(av[ii], bv[jj], acc[ii][jj]);
    }

    if (tx < 8) {
        float4 bb0 = *(const float4*)&b1[cc];
        float4 bb1 = *(const float4*)&b1[cc + 4];
        float bb[8] = {bb0.x, bb0.y, bb0.z, bb0.w, bb1.x, bb1.y, bb1.z, bb1.w};
        #pragma unroll
        for (int ii = 0; ii < 8; ii++) {
            float4 o0 = {acc[ii][0] + bb[0], acc[ii][1] + bb[1],
                         acc[ii][2] + bb[2], acc[ii][3] + bb[3]};
            float4 o1 = {acc[ii][4] + bb[4], acc[ii][5] + bb[5],
                         acc[ii][6] + bb[6], acc[ii][7] + bb[7]};
            *(float4*)&g_C[(v0 + rr + ii) * HID + cc]     = o0;
            *(float4*)&g_C[(v0 + rr + ii) * HID + cc + 4] = o1;
        }
    } else {
        #pragma unroll
        for (int ii = 0; ii < 8; ii++) {
            float4 o0 = {acc[ii][0], acc[ii][1], acc[ii][2], acc[ii][3]};
            float4 o1 = {acc[ii][4], acc[ii][5], acc[ii][6], acc[ii][7]};
            *(float4*)&g_P[(v0 + rr + ii) * HID + cc - 64]     = o0;
            *(float4*)&g_P[(v0 + rr + ii) * HID + cc - 64 + 4] = o1;
        }
    }
}

// ---------------- kernel 5: edge MLP via tf32 mma.sync + max aggregate ----------------
// Block: 4 vertices -> 128 edge rows (30 real + 2 pad each). 8 warps:
// warp w covers rows [16w, 16w+16) = vertex w/2, half (w&1).
// smem (floats): Wf2[4096] Wf3[4096] h1s[128*HS] h2s[128*HS] Cs[256] bs[128] part[512]
#define HS 68
#define O_WF2 0
#define O_WF3 4096
#define O_H1  8192
#define O_H2  (O_H1 + 128 * HS)
#define O_CS  (O_H2 + 128 * HS)
#define O_BS  (O_CS + 256)
#define O_PT  (O_BS + 128)
#define EDGE_SMEM_WORDS (O_PT + 512)

__global__ __launch_bounds__(256, 2) void edge_kernel(const float* __restrict__ W2,
                                                      const float* __restrict__ b2,
                                                      const float* __restrict__ W3,
                                                      const float* __restrict__ b3,
                                                      float* __restrict__ out) {
    extern __shared__ __align__(16) float sm[];
    unsigned* Wf2 = (unsigned*)(sm + O_WF2);
    unsigned* Wf3 = (unsigned*)(sm + O_WF3);
    float* h1s = sm + O_H1;
    float* h2s = sm + O_H2;
    float* Cs  = sm + O_CS;
    float* bs  = sm + O_BS;
    float* part = sm + O_PT;

    const int v0 = blockIdx.x * 4;
    const int tid = threadIdx.x;

    // stage W2/W3 in B-fragment layout (tf32-converted):
    // frag index (nt, s, lane): b0 = W[s*8+tig][nt*8+gid], b1 = W[s*8+tig+4][nt*8+gid]
    for (int t = tid; t < 2048; t += 256) {
        int lane = t & 31, s = (t >> 5) & 7, nt = t >> 8;
        int tig = lane & 3, gid = lane >> 2;
        int r = s * 8 + tig, c = nt * 8 + gid;
        Wf2[t * 2]     = f2tf(W2[r * 64 + c]);
        Wf2[t * 2 + 1] = f2tf(W2[(r + 4) * 64 + c]);
        Wf3[t * 2]     = f2tf(W3[r * 64 + c]);
        Wf3[t * 2 + 1] = f2tf(W3[(r + 4) * 64 + c]);
    }
    Cs[tid] = g_C[v0 * HID + tid];
    if (tid < 64) { bs[tid] = b2[tid]; bs[64 + tid] = b3[tid]; }
    __syncthreads();

    // layer 1: h1 = relu(C[v] - P[nbr]); pad rows (edges 30,31) = 0
    for (int t = tid; t < 4 * 32 * 64; t += 256) {
        int v = t >> 11, e = (t >> 6) & 31, i = t & 63;
        float h = 0.0f;
        if (e < KNN) {
            int nbr = g_idx[(v0 + v) * KNN + e];
            h = fmaxf(Cs[v * 64 + i] - g_P[nbr * HID + i], 0.0f);
        }
        h1s[(v * 32 + e) * HS + i] = h;
    }
    __syncthreads();

    const int w = tid >> 5, lane = tid & 31;
    const int tig = lane & 3, gid = lane >> 2;
    const int vl = w >> 1, sub = w & 1;
    const int rowbase = vl * 32 + sub * 16;

    // ---- layer 2: h2 = relu(h1 @ W2 + b2) ----
    {
        const float* hA = h1s + rowbase * HS;
        unsigned a[8][4];
        #pragma unroll
        for (int s = 0; s < 8; s++) {
            a[s][0] = f2tf(hA[gid * HS + 8 * s + tig]);
            a[s][1] = f2tf(hA[(gid + 8) * HS + 8 * s + tig]);
            a[s][2] = f2tf(hA[gid * HS + 8 * s + tig + 4]);
            a[s][3] = f2tf(hA[(gid + 8) * HS + 8 * s + tig + 4]);
        }
        #pragma unroll
        for (int nt = 0; nt < 8; nt++) {
            float bv0 = bs[nt * 8 + 2 * tig], bv1 = bs[nt * 8 + 2 * tig + 1];
            float c0 = bv0, c1 = bv1, c2 = bv0, c3 = bv1;
            #pragma unroll
            for (int s = 0; s < 8; s++) {
                float2 bf = *(const float2*)&Wf2[((nt * 8 + s) * 32 + lane) * 2];
                mma1688(c0, c1, c2, c3, a[s][0], a[s][1], a[s][2], a[s][3],
                        __float_as_uint(bf.x), __float_as_uint(bf.y));
            }
            float2 lo = {fmaxf(c0, 0.f), fmaxf(c1, 0.f)};
            float2 hi = {fmaxf(c2, 0.f), fmaxf(c3, 0.f)};
            *(float2*)&h2s[(rowbase + gid) * HS + nt * 8 + 2 * tig]     = lo;
            *(float2*)&h2s[(rowbase + gid + 8) * HS + nt * 8 + 2 * tig] = hi;
        }
    }
    __syncthreads();

    // ---- layer 3 + masked max over edges ----
    {
        const float* hA = h2s + rowbase * HS;
        unsigned a[8][4];
        #pragma unroll
        for (int s = 0; s < 8; s++) {
            a[s][0] = f2tf(hA[gid * HS + 8 * s + tig]);
            a[s][1] = f2tf(hA[(gid + 8) * HS + 8 * s + tig]);
            a[s][2] = f2tf(hA[gid * HS + 8 * s + tig + 4]);
            a[s][3] = f2tf(hA[(gid + 8) * HS + 8 * s + tig + 4]);
        }
        const bool pad = (sub == 1) && (gid >= 6);   // vertex rows 30,31
        #pragma unroll
        for (int nt = 0; nt < 8; nt++) {
            float bv0 = bs[64 + nt * 8 + 2 * tig], bv1 = bs[64 + nt * 8 + 2 * tig + 1];
            float c0 = bv0, c1 = bv1, c2 = bv0, c3 = bv1;
            #pragma unroll
            for (int s = 0; s < 8; s++) {
                float2 bf = *(const float2*)&Wf3[((nt * 8 + s) * 32 + lane) * 2];
                mma1688(c0, c1, c2, c3, a[s][0], a[s][1], a[s][2], a[s][3],
                        __float_as_uint(bf.x), __float_as_uint(bf.y));
            }
            float m0 = fmaxf(c0, 0.f), m1 = fmaxf(c1, 0.f);
            float u0 = fmaxf(c2, 0.f), u1 = fmaxf(c3, 0.f);
            if (pad) { u0 = -1e30f; u1 = -1e30f; }
            m0 = fmaxf(m0, u0); m1 = fmaxf(m1, u1);
            #pragma unroll
            for (int off = 4; off < 32; off <<= 1) {
                m0 = fmaxf(m0, __shfl_xor_sync(0xFFFFFFFFu, m0, off));
                m1 = fmaxf(m1, __shfl_xor_sync(0xFFFFFFFFu, m1, off));
            }
            if (gid == 0) {
                part[w * 64 + nt * 8 + 2 * tig]     = m0;
                part[w * 64 + nt * 8 + 2 * tig + 1] = m1;
            }
        }
    }
    __syncthreads();

    {
        int v = tid >> 6, col = tid & 63;
        float m = fmaxf(part[(2 * v) * 64 + col], part[(2 * v + 1) * 64 + col]);
        out[(v0 + v) * HID + col] = m;
    }
}

// ---------------- launch ----------------
extern "C" void kernel_launch(void* const* d_in, const int* in_sizes, int n_in,
                              void* d_out, int out_size) {
    (void)in_sizes; (void)n_in; (void)out_size;
    const float* x  = (const float*)d_in[0];
    const float* W1 = (const float*)d_in[2];
    const float* b1 = (const float*)d_in[3];
    const float* W2 = (const float*)d_in[4];
    const float* b2 = (const float*)d_in[5];
    const float* W3 = (const float*)d_in[6];
    const float* b3 = (const float*)d_in[7];
    float* out = (float*)d_out;

    const int GEMM_SMEM = 2 * 64 * TS * 4;            // 69632 B
    const int EDGE_SMEM = EDGE_SMEM_WORDS * 4;        // ~106 KB
    static bool attr_done = false;
    if (!attr_done) {
        cudaFuncSetAttribute(dist_kernel, cudaFuncAttributeMaxDynamicSharedMemorySize, GEMM_SMEM);
        cudaFuncSetAttribute(cp_kernel,   cudaFuncAttributeMaxDynamicSharedMemorySize, GEMM_SMEM);
        cudaFuncSetAttribute(edge_kernel, cudaFuncAttributeMaxDynamicSharedMemorySize, EDGE_SMEM);
        attr_done = true;
    }

    sq_kernel<<<NPTS / 8, dim3(32, 8)>>>(x);
    dist_kernel<<<dim3(136, BATCH), 256, GEMM_SMEM>>>(x);
    select_kernel<<<NPTS / 8, 256>>>();
    cp_kernel<<<NPTS / 128, 256, GEMM_SMEM>>>(x, W1, b1);
    edge_kernel<<<NPTS / 4, 256, EDGE_SMEM>>>(W2, b2, W3, b3, out);
}

// round 15
// speedup vs baseline: 2.9077x; 1.1453x over previous
#include <cuda_runtime.h>

#define BATCH 16
#define V     2048
#define F     64
#define HID   64
#define KNN   30
#define NPTS  (BATCH * V)   // 32768

// ---------------- device scratch ----------------
__device__ float g_dist[(size_t)BATCH * V * V];   // 256 MB
__device__ float g_sq[NPTS];
__device__ int   g_idx[NPTS * KNN];
__device__ float g_C[NPTS * HID];   // x @ (W1a+W1b) + b1
__device__ float g_P[NPTS * HID];   // x @ W1b
__device__ unsigned g_Wf2[4096];    // W2 in tf32 B-fragment layout
__device__ unsigned g_Wf3[4096];    // W3 in tf32 B-fragment layout

// ---------------- tf32 helpers ----------------
__device__ __forceinline__ unsigned f2tf(float x) {
    unsigned r; asm("cvt.rna.tf32.f32 %0, %1;" : "=r"(r) : "f"(x)); return r;
}
__device__ __forceinline__ void mma1688(float& c0, float& c1, float& c2, float& c3,
                                        unsigned a0, unsigned a1, unsigned a2, unsigned a3,
                                        unsigned b0, unsigned b1) {
    asm("mma.sync.aligned.m16n8k8.row.col.f32.tf32.tf32.f32 "
        "{%0,%1,%2,%3},{%4,%5,%6,%7},{%8,%9},{%0,%1,%2,%3};"
        : "+f"(c0), "+f"(c1), "+f"(c2), "+f"(c3)
        : "r"(a0), "r"(a1), "r"(a2), "r"(a3), "r"(b0), "r"(b1));
}

// ---------------- kernel 0: pre-fragment W2/W3 (runs once per launch) ----------------
// frag index (nt, s, lane): b0 = W[8s+tig][8nt+gid], b1 = W[8s+tig+4][8nt+gid]
__global__ void wprep_kernel(const float* __restrict__ W2, const float* __restrict__ W3) {
    int t = blockIdx.x * 256 + threadIdx.x;   // 0..2047
    int lane = t & 31, s = (t >> 5) & 7, nt = t >> 8;
    int tig = lane & 3, gid = lane >> 2;
    int r = s * 8 + tig, c = nt * 8 + gid;
    g_Wf2[t * 2]     = f2tf(W2[r * 64 + c]);
    g_Wf2[t * 2 + 1] = f2tf(W2[(r + 4) * 64 + c]);
    g_Wf3[t * 2]     = f2tf(W3[r * 64 + c]);
    g_Wf3[t * 2 + 1] = f2tf(W3[(r + 4) * 64 + c]);
}

// ---------------- kernel 1: squared norms ----------------
__global__ void sq_kernel(const float* __restrict__ x) {
    int v = blockIdx.x * 8 + threadIdx.y;
    int l = threadIdx.x;
    float a = x[v * F + l];
    float b = x[v * F + 32 + l];
    float s = a * a + b * b;
    #pragma unroll
    for (int o = 16; o; o >>= 1) s += __shfl_xor_sync(0xFFFFFFFFu, s, o);
    if (l == 0) g_sq[v] = s;
}

// ---------------- kernel 2: symmetric distance GEMM (fp32, exact) ----------------
#define TS 136
__global__ __launch_bounds__(256) void dist_kernel(const float* __restrict__ x) {
    extern __shared__ __align__(16) float sm[];
    float* Xi = sm;
    float* Xj = sm + 64 * TS;
    const int b = blockIdx.y;
    int p = blockIdx.x, ti = 0;
    while (p >= 16 - ti) { p -= 16 - ti; ti++; }
    const int tj = ti + p;
    const int i0 = ti * 128, j0 = tj * 128;
    const int tid = threadIdx.x;
    const float* xb = x + (size_t)b * V * F;

    for (int t = tid; t < 8192; t += 256) {
        int f = t & 63, v = t >> 6;
        Xi[f * TS + v] = xb[(i0 + v) * F + f];
        Xj[f * TS + v] = xb[(j0 + v) * F + f];
    }
    __syncthreads();

    const int tx = tid & 15, ty = tid >> 4;
    const int rr = ty * 8, cc = tx * 8;
    float acc[8][8] = {};

    #pragma unroll 8
    for (int k = 0; k < 64; k++) {
        float4 a0 = *(const float4*)&Xi[k * TS + rr];
        float4 a1 = *(const float4*)&Xi[k * TS + rr + 4];
        float4 c0 = *(const float4*)&Xj[k * TS + cc];
        float4 c1 = *(const float4*)&Xj[k * TS + cc + 4];
        float av[8] = {a0.x, a0.y, a0.z, a0.w, a1.x, a1.y, a1.z, a1.w};
        float bv[8] = {c0.x, c0.y, c0.z, c0.w, c1.x, c1.y, c1.z, c1.w};
        #pragma unroll
        for (int ii = 0; ii < 8; ii++)
            #pragma unroll
            for (int jj = 0; jj < 8; jj++)
                acc[ii][jj] = fmaf(av[ii], bv[jj], acc[ii][jj]);
    }

    float sqi[8], sqj[8];
    #pragma unroll
    for (int u = 0; u < 8; u++) {
        sqi[u] = g_sq[b * V + i0 + rr + u];
        sqj[u] = g_sq[b * V + j0 + cc + u];
    }
    float* db = g_dist + (size_t)b * V * V;
    #pragma unroll
    for (int ii = 0; ii < 8; ii++) {
        float4 o0, o1;
        o0.x = sqi[ii] + sqj[0] - 2.0f * acc[ii][0];
        o0.y = sqi[ii] + sqj[1] - 2.0f * acc[ii][1];
        o0.z = sqi[ii] + sqj[2] - 2.0f * acc[ii][2];
        o0.w = sqi[ii] + sqj[3] - 2.0f * acc[ii][3];
        o1.x = sqi[ii] + sqj[4] - 2.0f * acc[ii][4];
        o1.y = sqi[ii] + sqj[5] - 2.0f * acc[ii][5];
        o1.z = sqi[ii] + sqj[6] - 2.0f * acc[ii][6];
        o1.w = sqi[ii] + sqj[7] - 2.0f * acc[ii][7];
        *(float4*)&db[(size_t)(i0 + rr + ii) * V + j0 + cc]     = o0;
        *(float4*)&db[(size_t)(i0 + rr + ii) * V + j0 + cc + 4] = o1;
    }
    if (ti != tj) {
        #pragma unroll
        for (int jj = 0; jj < 8; jj++) {
            float4 o0, o1;
            o0.x = sqj[jj] + sqi[0] - 2.0f * acc[0][jj];
            o0.y = sqj[jj] + sqi[1] - 2.0f * acc[1][jj];
            o0.z = sqj[jj] + sqi[2] - 2.0f * acc[2][jj];
            o0.w = sqj[jj] + sqi[3] - 2.0f * acc[3][jj];
            o1.x = sqj[jj] + sqi[4] - 2.0f * acc[4][jj];
            o1.y = sqj[jj] + sqi[5] - 2.0f * acc[5][jj];
            o1.z = sqj[jj] + sqi[6] - 2.0f * acc[6][jj];
            o1.w = sqj[jj] + sqi[7] - 2.0f * acc[7][jj];
            *(float4*)&db[(size_t)(j0 + cc + jj) * V + i0 + rr]     = o0;
            *(float4*)&db[(size_t)(j0 + cc + jj) * V + i0 + rr + 4] = o1;
        }
    }
}

// ---------------- kernel 3: warp-per-row top-31 selection ----------------
__global__ __launch_bounds__(256) void select_kernel() {
    const int warp = threadIdx.x >> 5, lane = threadIdx.x & 31;
    const int q = blockIdx.x * 8 + warp;
    const float4* r4 = (const float4*)(g_dist + (size_t)q * V);

    float v[64];
    #pragma unroll
    for (int s = 0; s < 16; s++) {
        float4 t = r4[s * 32 + lane];
        v[s * 4 + 0] = t.x; v[s * 4 + 1] = t.y;
        v[s * 4 + 2] = t.z; v[s * 4 + 3] = t.w;
    }
    unsigned long long removed = 0ULL;
    float b1v = v[0], b2v = 3.4e38f;
    int b1p = 0, b2p = 0;
    #pragma unroll
    for (int p = 1; p < 64; p++) {
        float xv = v[p];
        if (xv < b1v)      { b2v = b1v; b2p = b1p; b1v = xv; b1p = p; }
        else if (xv < b2v) { b2v = xv; b2p = p; }
    }
    bool b2ok = true;
    const int base = (q >> 11) << 11;

    #pragma unroll 1
    for (int it = 0; it < KNN + 1; it++) {
        float bv = b1v;
        int bj = ((b1p >> 2) << 7) + (lane << 2) + (b1p & 3);
        #pragma unroll
        for (int off = 16; off; off >>= 1) {
            float ov = __shfl_xor_sync(0xFFFFFFFFu, bv, off);
            int   oj = __shfl_xor_sync(0xFFFFFFFFu, bj, off);
            if (ov < bv || (ov == bv && oj < bj)) { bv = ov; bj = oj; }
        }
        if (it > 0 && lane == 0) g_idx[q * KNN + it - 1] = base + bj;
        int wl = (bj >> 2) & 31;
        if (lane == wl) {
            int pw = ((bj >> 7) << 2) | (bj & 3);
            removed |= 1ULL << pw;
            if (b2ok) { b1v = b2v; b1p = b2p; b2ok = false; }
            else {
                b1v = 3.4e38f; b2v = 3.4e38f; b1p = 0; b2p = 0;
                #pragma unroll
                for (int pp = 0; pp < 64; pp++) {
                    if (!((removed >> pp) & 1ULL)) {
                        float xv = v[pp];
                        if (xv < b1v)      { b2v = b1v; b2p = b1p; b1v = xv; b1p = pp; }
                        else if (xv < b2v) { b2v = xv; b2p = pp; }
                    }
                }
                b2ok = true;
            }
        }
    }
}

// ---------------- kernel 4: cp as 128x128 GEMM tile (fp32, exact) ----------------
__global__ __launch_bounds__(256) void cp_kernel(const float* __restrict__ x,
                                                 const float* __restrict__ W1,
                                                 const float* __restrict__ b1) {
    extern __shared__ __align__(16) float sm[];
    float* Xs = sm;
    float* Ws = sm + 64 * TS;
    const int v0 = blockIdx.x * 128;
    const int tid = threadIdx.x;

    for (int t = tid; t < 8192; t += 256) {
        int f = t & 63, v = t >> 6;
        Xs[f * TS + v] = x[(v0 + v) * F + f];
    }
    for (int t = tid; t < 4096; t += 256) {
        int f = t >> 6, j = t & 63;
        float wb = W1[(F + f) * HID + j];
        Ws[f * TS + j]      = W1[f * HID + j] + wb;
        Ws[f * TS + 64 + j] = wb;
    }
    __syncthreads();

    const int tx = tid & 15, ty = tid >> 4;
    const int rr = ty * 8, cc = tx * 8;
    float acc[8][8] = {};
    #pragma unroll 8
    for (int k = 0; k < 64; k++) {
        float4 a0 = *(const float4*)&Xs[k * TS + rr];
        float4 a1 = *(const float4*)&Xs[k * TS + rr + 4];
        float4 c0 = *(const float4*)&Ws[k * TS + cc];
        float4 c1 = *(const float4*)&Ws[k * TS + cc + 4];
        float av[8] = {a0.x, a0.y, a0.z, a0.w, a1.x, a1.y, a1.z, a1.w};
        float bv[8] = {c0.x, c0.y, c0.z, c0.w, c1.x, c1.y, c1.z, c1.w};
        #pragma unroll
        for (int ii = 0; ii < 8; ii++)
            #pragma unroll
            for (int jj = 0; jj < 8; jj++)
                acc[ii][jj] = fmaf(av[ii], bv[jj], acc[ii][jj]);
    }

    if (tx < 8) {
        float4 bb0 = *(const float4*)&b1[cc];
        float4 bb1 = *(const float4*)&b1[cc + 4];
        float bb[8] = {bb0.x, bb0.y, bb0.z, bb0.w, bb1.x, bb1.y, bb1.z, bb1.w};
        #pragma unroll
        for (int ii = 0; ii < 8; ii++) {
            float4 o0 = {acc[ii][0] + bb[0], acc[ii][1] + bb[1],
                         acc[ii][2] + bb[2], acc[ii][3] + bb[3]};
            float4 o1 = {acc[ii][4] + bb[4], acc[ii][5] + bb[5],
                         acc[ii][6] + bb[6], acc[ii][7] + bb[7]};
            *(float4*)&g_C[(v0 + rr + ii) * HID + cc]     = o0;
            *(float4*)&g_C[(v0 + rr + ii) * HID + cc + 4] = o1;
        }
    } else {
        #pragma unroll
        for (int ii = 0; ii < 8; ii++) {
            float4 o0 = {acc[ii][0], acc[ii][1], acc[ii][2], acc[ii][3]};
            float4 o1 = {acc[ii][4], acc[ii][5], acc[ii][6], acc[ii][7]};
            *(float4*)&g_P[(v0 + rr + ii) * HID + cc - 64]     = o0;
            *(float4*)&g_P[(v0 + rr + ii) * HID + cc - 64 + 4] = o1;
        }
    }
}

// ---------------- kernel 5: edge MLP via tf32 mma.sync + max aggregate ----------------
// Block: 8 vertices -> 256 edge rows, 512 threads / 16 warps.
// Warp w: vertex w/2, half w&1, rows [rowbase, rowbase+16).
// Weights read directly from pre-fragmented g_Wf2/g_Wf3 (L1-resident broadcast).
// Single h buffer: layer-2 output overwrites layer-1 rows (A-frags are
// register-resident before the store; each warp touches only its own rows).
#define HS 68
#define O_H   0                       // 256*HS = 17408 words
#define O_CS  (256 * HS)              // 512
#define O_BS  (O_CS + 512)            // 128
#define O_PT  (O_BS + 128)            // 1024
#define EDGE_SMEM_WORDS (O_PT + 1024) // 19072 words = 76288 B

__global__ __launch_bounds__(512, 2) void edge_kernel(const float* __restrict__ b2,
                                                      const float* __restrict__ b3,
                                                      float* __restrict__ out) {
    extern __shared__ __align__(16) float sm[];
    float* hs  = sm + O_H;
    float* Cs  = sm + O_CS;
    float* bs  = sm + O_BS;
    float* part = sm + O_PT;

    const int v0 = blockIdx.x * 8;
    const int tid = threadIdx.x;

    Cs[tid] = g_C[v0 * HID + tid];                      // 8 verts x 64
    if (tid < 64) { bs[tid] = b2[tid]; bs[64 + tid] = b3[tid]; }
    __syncthreads();   // Cs ready before layer-1 reads it

    // layer 1: h = relu(C[v] - P[nbr]); pad rows (edges 30,31) = 0
    for (int t = tid; t < 8 * 32 * 64; t += 512) {
        int v = t >> 11, e = (t >> 6) & 31, i = t & 63;
        float h = 0.0f;
        if (e < KNN) {
            int nbr = g_idx[(v0 + v) * KNN + e];
            h = fmaxf(Cs[v * 64 + i] - g_P[nbr * HID + i], 0.0f);
        }
        hs[(v * 32 + e) * HS + i] = h;
    }
    __syncthreads();

    const int w = tid >> 5, lane = tid & 31;
    const int tig = lane & 3, gid = lane >> 2;
    const int sub = w & 1;
    const int rowbase = (w >> 1) * 32 + sub * 16;
    const float* hA = hs + rowbase * HS;
    const uint2* wf2 = (const uint2*)g_Wf2;
    const uint2* wf3 = (const uint2*)g_Wf3;

    // ---- layer 2: h <- relu(h @ W2 + b2) (in place, warp-local rows) ----
    {
        unsigned a[8][4];
        #pragma unroll
        for (int s = 0; s < 8; s++) {
            a[s][0] = f2tf(hA[gid * HS + 8 * s + tig]);
            a[s][1] = f2tf(hA[(gid + 8) * HS + 8 * s + tig]);
            a[s][2] = f2tf(hA[gid * HS + 8 * s + tig + 4]);
            a[s][3] = f2tf(hA[(gid + 8) * HS + 8 * s + tig + 4]);
        }
        #pragma unroll
        for (int nt = 0; nt < 8; nt++) {
            float bv0 = bs[nt * 8 + 2 * tig], bv1 = bs[nt * 8 + 2 * tig + 1];
            float c0 = bv0, c1 = bv1, c2 = bv0, c3 = bv1;
            #pragma unroll
            for (int s = 0; s < 8; s++) {
                uint2 bf = wf2[(nt * 8 + s) * 32 + lane];
                mma1688(c0, c1, c2, c3, a[s][0], a[s][1], a[s][2], a[s][3],
                        bf.x, bf.y);
            }
            float2 lo = {fmaxf(c0, 0.f), fmaxf(c1, 0.f)};
            float2 hi = {fmaxf(c2, 0.f), fmaxf(c3, 0.f)};
            *(float2*)&hs[(rowbase + gid) * HS + nt * 8 + 2 * tig]     = lo;
            *(float2*)&hs[(rowbase + gid + 8) * HS + nt * 8 + 2 * tig] = hi;
        }
    }
    __syncwarp();   // layer-2 stores visible to this warp's layer-3 loads

    // ---- layer 3 + masked max over edges ----
    {
        unsigned a[8][4];
        #pragma unroll
        for (int s = 0; s < 8; s++) {
            a[s][0] = f2tf(hA[gid * HS + 8 * s + tig]);
            a[s][1] = f2tf(hA[(gid + 8) * HS + 8 * s + tig]);
            a[s][2] = f2tf(hA[gid * HS + 8 * s + tig + 4]);
            a[s][3] = f2tf(hA[(gid + 8) * HS + 8 * s + tig + 4]);
        }
        const bool pad = (sub == 1) && (gid >= 6);   // vertex rows 30,31
        #pragma unroll
        for (int nt = 0; nt < 8; nt++) {
            float bv0 = bs[64 + nt * 8 + 2 * tig], bv1 = bs[64 + nt * 8 + 2 * tig + 1];
            float c0 = bv0, c1 = bv1, c2 = bv0, c3 = bv1;
            #pragma unroll
            for (int s = 0; s < 8; s++) {
                uint2 bf = wf3[(nt * 8 + s) * 32 + lane];
                mma1688(c0, c1, c2, c3, a[s][0], a[s][1], a[s][2], a[s][3],
                        bf.x, bf.y);
            }
            float m0 = fmaxf(c0, 0.f), m1 = fmaxf(c1, 0.f);
            float u0 = fmaxf(c2, 0.f), u1 = fmaxf(c3, 0.f);
            if (pad) { u0 = -1e30f; u1 = -1e30f; }
            m0 = fmaxf(m0, u0); m1 = fmaxf(m1, u1);
            #pragma unroll
            for (int off = 4; off < 32; off <<= 1) {
                m0 = fmaxf(m0, __shfl_xor_sync(0xFFFFFFFFu, m0, off));
                m1 = fmaxf(m1, __shfl_xor_sync(0xFFFFFFFFu, m1, off));
            }
            if (gid == 0) {
                part[w * 64 + nt * 8 + 2 * tig]     = m0;
                part[w * 64 + nt * 8 + 2 * tig + 1] = m1;
            }
        }
    }
    __syncthreads();

    {
        int v = tid >> 6, col = tid & 63;
        float m = fmaxf(part[(2 * v) * 64 + col], part[(2 * v + 1) * 64 + col]);
        out[(v0 + v) * HID + col] = m;
    }
}

// ---------------- launch ----------------
extern "C" void kernel_launch(void* const* d_in, const int* in_sizes, int n_in,
                              void* d_out, int out_size) {
    (void)in_sizes; (void)n_in; (void)out_size;
    const float* x  = (const float*)d_in[0];
    const float* W1 = (const float*)d_in[2];
    const float* b1 = (const float*)d_in[3];
    const float* W2 = (const float*)d_in[4];
    const float* b2 = (const float*)d_in[5];
    const float* W3 = (const float*)d_in[6];
    const float* b3 = (const float*)d_in[7];
    float* out = (float*)d_out;

    const int GEMM_SMEM = 2 * 64 * TS * 4;            // 69632 B
    const int EDGE_SMEM = EDGE_SMEM_WORDS * 4;        // 76288 B
    static bool attr_done = false;
    if (!attr_done) {
        cudaFuncSetAttribute(dist_kernel, cudaFuncAttributeMaxDynamicSharedMemorySize, GEMM_SMEM);
        cudaFuncSetAttribute(cp_kernel,   cudaFuncAttributeMaxDynamicSharedMemorySize, GEMM_SMEM);
        cudaFuncSetAttribute(edge_kernel, cudaFuncAttributeMaxDynamicSharedMemorySize, EDGE_SMEM);
        attr_done = true;
    }

    wprep_kernel<<<8, 256>>>(W2, W3);
    sq_kernel<<<NPTS / 8, dim3(32, 8)>>>(x);
    dist_kernel<<<dim3(136, BATCH), 256, GEMM_SMEM>>>(x);
    select_kernel<<<NPTS / 8, 256>>>();
    cp_kernel<<<NPTS / 128, 256, GEMM_SMEM>>>(x, W1, b1);
    edge_kernel<<<NPTS / 8, 512, EDGE_SMEM>>>(b2, b3, out);
}